// round 6
// baseline (speedup 1.0000x reference)
#include <cuda_runtime.h>
#include <cuda_bf16.h>
#include <cuda_fp16.h>
#include <cstdint>

// Problem constants
#define Bn 4
#define Np 4096      // pixels per batch (64*64)
#define Cc 512
#define NW 640       // packed QKV output width: 64 f + 64 g + 512 v
#define NROWS (Bn*Np)
#define PSCALE 0.0625f   // P stored as exp(s)/16; cancels in P@V / rowsum(P)

// Scratch (static device allocations -- allowed)
__device__ __align__(1024) __half g_Xb[(size_t)NROWS * Cc];   // x in fp16
__device__ __align__(1024) __half g_Wt[(size_t)NW * Cc];      // packed weights [n][k]
__device__ __align__(1024) __half g_FG[(size_t)NROWS * 128];  // f (0-63), g (64-127)
__device__ __align__(1024) __half g_V [(size_t)Bn * Np * Cc]; // V natural [b][i][c]
__device__ __align__(1024) __half g_Vt[(size_t)Bn * Cc * Np]; // V transposed [b][c][i]
__device__ __align__(1024) __half g_P [(size_t)Bn * Np * Np]; // exp(S)/16, fp16
__device__ float g_l[NROWS];                                  // row sums of stored P

// ---------------------------------------------------------------------------
// mma.sync m16n8k16 fp16 -> fp16 accum (2x rate vs f32 accum)
// ---------------------------------------------------------------------------
__device__ __forceinline__ void mma_f16(uint32_t c[2], const uint32_t a[4],
                                        uint32_t b0, uint32_t b1) {
    asm volatile(
        "mma.sync.aligned.m16n8k16.row.col.f16.f16.f16.f16 "
        "{%0,%1}, {%2,%3,%4,%5}, {%6,%7}, {%0,%1};\n"
        : "+r"(c[0]), "+r"(c[1])
        : "r"(a[0]), "r"(a[1]), "r"(a[2]), "r"(a[3]), "r"(b0), "r"(b1));
}
__device__ __forceinline__ void ldsm4(uint32_t& r0, uint32_t& r1, uint32_t& r2,
                                      uint32_t& r3, uint32_t addr) {
    asm volatile("ldmatrix.sync.aligned.m8n8.x4.shared.b16 {%0,%1,%2,%3}, [%4];"
                 : "=r"(r0), "=r"(r1), "=r"(r2), "=r"(r3) : "r"(addr));
}
__device__ __forceinline__ uint32_t smem_to_u32(const void* p) {
    uint32_t a;
    asm("{ .reg .u64 t; cvta.to.shared.u64 t, %1; cvt.u32.u64 %0, t; }" : "=r"(a) : "l"(p));
    return a;
}
__device__ __forceinline__ void cp16(uint32_t dst, const void* src) {
    asm volatile("cp.async.cg.shared.global [%0], [%1], 16;\n" :: "r"(dst), "l"(src));
}
#define CP_COMMIT() asm volatile("cp.async.commit_group;\n" ::: "memory")
#define CP_WAIT(n)  asm volatile("cp.async.wait_group %0;\n" :: "n"(n) : "memory")

#define TK  64
#define SA  72                        // smem row stride in fp16 (conflict-free)
#define STG (128 * SA)                // elements per staged tile (A or B)
#define NS  3                         // pipeline stages
#define GEMM_SMEM (NS * 2 * STG * 2)  // bytes = 110592

// Block tile 128x128, K-tile 64, 256 threads (8 warps, 4x2 grid, 32x64 each).
// cp.async 3-stage pipeline, single barrier per K-iter, ks-pipelined ldmatrix.
// acc[ii][j][h]: half2 pair (cols 2t4..2t4+1) at rows (+0 / +8).
__device__ __forceinline__ void gemm_tile(
    const __half* __restrict__ Ag, int lda,
    const __half* __restrict__ Bg, int ldb,
    int K, uint32_t acc[2][8][2], __half* smem)
{
    const int tid = threadIdx.x, lane = tid & 31, warp = tid >> 5;
    const int wm = warp & 3, wn = warp >> 2;
    const uint32_t sbase = smem_to_u32(smem);
    const int r0 = tid >> 3;            // staging row 0..31 (+32*rr)
    const int c0 = (tid & 7) << 3;      // staging col {0..56}
    const int nk = K / TK;

    // Per-lane ldmatrix base byte-offsets within a stage buffer.
    const uint32_t offA0 = (uint32_t)((wm * 32 + ((lane >> 3) & 1) * 8 + (lane & 7)) * SA
                                      + (lane >> 4) * 8) * 2;
    const uint32_t offA1 = offA0 + 16 * SA * 2;
    const uint32_t offB0 = (uint32_t)(STG + (wn * 64 + (lane >> 4) * 8 + (lane & 7)) * SA
                                      + ((lane >> 3) & 1) * 8) * 2;

    auto issue = [&](int i) {
        const int s = i % NS;
        const uint32_t sa = sbase + (uint32_t)(s * 2 * STG) * 2;
        const uint32_t sb = sa + STG * 2;
        const int k0 = i * TK;
        #pragma unroll
        for (int rr = 0; rr < 4; rr++) {
            const int row = rr * 32 + r0;
            cp16(sa + (row * SA + c0) * 2, Ag + (size_t)row * lda + k0 + c0);
            cp16(sb + (row * SA + c0) * 2, Bg + (size_t)row * ldb + k0 + c0);
        }
        CP_COMMIT();
    };

    auto ldfr = [&](uint32_t bb, int ks, uint32_t a[2][4], uint32_t b4[4][4]) {
        const uint32_t kofs = (uint32_t)ks * 32;   // 16 fp16 = 32 bytes
        ldsm4(a[0][0], a[0][1], a[0][2], a[0][3], bb + offA0 + kofs);
        ldsm4(a[1][0], a[1][1], a[1][2], a[1][3], bb + offA1 + kofs);
        #pragma unroll
        for (int jp = 0; jp < 4; jp++)
            ldsm4(b4[jp][0], b4[jp][1], b4[jp][2], b4[jp][3],
                  bb + offB0 + (uint32_t)(jp * 16 * SA * 2) + kofs);
    };

    // Prologue: fill up to NS-1 stages
    #pragma unroll
    for (int p = 0; p < NS - 1; p++)
        if (p < nk) issue(p);

    for (int i = 0; i < nk; i++) {
        if (i < nk - 1) CP_WAIT(1); else CP_WAIT(0);
        __syncthreads();                       // single barrier per iteration
        if (i + NS - 1 < nk) issue(i + NS - 1);

        const uint32_t bb = sbase + (uint32_t)((i % NS) * 2 * STG) * 2;
        uint32_t a[2][2][4], b4[2][4][4];
        ldfr(bb, 0, a[0], b4[0]);
        #pragma unroll
        for (int ks = 0; ks < 4; ks++) {       // four k16 steps per K-tile
            const int cur = ks & 1, nxt = cur ^ 1;
            if (ks < 3) ldfr(bb, ks + 1, a[nxt], b4[nxt]);
            #pragma unroll
            for (int ii = 0; ii < 2; ii++)
                #pragma unroll
                for (int jp = 0; jp < 4; jp++) {
                    mma_f16(acc[ii][2 * jp],     a[cur][ii], b4[cur][jp][0], b4[cur][jp][1]);
                    mma_f16(acc[ii][2 * jp + 1], a[cur][ii], b4[cur][jp][2], b4[cur][jp][3]);
                }
        }
    }
    __syncthreads();   // protect final buffers before caller reuses smem
}

// ---------------------------------------------------------------------------
// Prep kernels
// ---------------------------------------------------------------------------
__global__ void convert_x(const float* __restrict__ x) {
    size_t i = (size_t)blockIdx.x * 256 + threadIdx.x;
    float4 v = ((const float4*)x)[i];
    __half2 p0 = __floats2half2_rn(v.x, v.y);
    __half2 p1 = __floats2half2_rn(v.z, v.w);
    ((__half2*)g_Xb)[2 * i]     = p0;
    ((__half2*)g_Xb)[2 * i + 1] = p1;
}

__global__ void pack_w(const float* __restrict__ kf, const float* __restrict__ kg,
                       const float* __restrict__ kh) {
    int idx = blockIdx.x * 256 + threadIdx.x;
    int n = idx >> 9, k = idx & 511;
    float v;
    if (n < 64)       v = kf[k * 64 + n];
    else if (n < 128) v = kg[k * 64 + (n - 64)];
    else              v = kh[k * 512 + (n - 128)];
    g_Wt[idx] = __float2half(v);
}

__global__ void zero_l() {
    int i = blockIdx.x * 1024 + threadIdx.x;
    if (i < NROWS) g_l[i] = 0.f;
}

// ---------------------------------------------------------------------------
// GEMM 1: [f|g|v] = Xb @ W ; f/g -> g_FG, v -> g_V (natural, coalesced)
// ---------------------------------------------------------------------------
__global__ void __launch_bounds__(256, 2) gemm1_qkv() {
    extern __shared__ __half smem[];
    uint32_t acc[2][8][2];
    #pragma unroll
    for (int i = 0; i < 2; i++)
        #pragma unroll
        for (int j = 0; j < 8; j++) { acc[i][j][0] = 0u; acc[i][j][1] = 0u; }

    const int m0 = blockIdx.y * 128, n0 = blockIdx.x * 128;
    gemm_tile(g_Xb + (size_t)m0 * Cc, Cc, g_Wt + (size_t)n0 * Cc, Cc, Cc, acc, smem);

    const int lane = threadIdx.x & 31, warp = threadIdx.x >> 5;
    const int wm = warp & 3, wn = warp >> 2, g = lane >> 2, t4 = lane & 3;
    #pragma unroll
    for (int i = 0; i < 2; i++) {
        #pragma unroll
        for (int h = 0; h < 2; h++) {
            int r = m0 + wm * 32 + i * 16 + g + h * 8;
            #pragma unroll
            for (int j = 0; j < 8; j++) {
                int c = n0 + wn * 64 + j * 8 + 2 * t4;
                uint32_t p = acc[i][j][h];          // half2 at (r, c..c+1)
                if (n0 == 0) *(uint32_t*)&g_FG[(size_t)r * 128 + c] = p;
                else         *(uint32_t*)&g_V [(size_t)r * Cc + (c - 128)] = p;
            }
        }
    }
}

// ---------------------------------------------------------------------------
// Transpose V [b][i][c] -> Vt [b][c][i] (smem tiled, coalesced both sides)
// ---------------------------------------------------------------------------
__global__ void vtrans() {
    __shared__ __half t[64 * 72];
    const int bb = blockIdx.z, it = blockIdx.x, ct = blockIdx.y;
    const __half* src = g_V + ((size_t)bb * Np + it * 64) * Cc + ct * 64;
    #pragma unroll
    for (int k = 0; k < 2; k++) {
        int u = threadIdx.x + k * 256;
        int row = u >> 3, c8 = (u & 7) * 8;
        *(uint4*)(t + row * 72 + c8) = *(const uint4*)(src + (size_t)row * Cc + c8);
    }
    __syncthreads();
    __half* dst = g_Vt + ((size_t)bb * Cc + ct * 64) * Np + it * 64;
    #pragma unroll
    for (int k = 0; k < 2; k++) {
        int u = threadIdx.x + k * 256;
        int orow = u >> 3, i8 = (u & 7) * 8;
        __half tmp[8];
        #pragma unroll
        for (int q = 0; q < 8; q++) tmp[q] = t[(i8 + q) * 72 + orow];
        *(uint4*)(dst + (size_t)orow * Np + i8) = *(uint4*)tmp;
    }
}

// ---------------------------------------------------------------------------
// GEMM 2: P = exp(F @ G^T)/16 per batch, + fused row-sum atomics
// ---------------------------------------------------------------------------
__global__ void __launch_bounds__(256, 2) gemm2_score() {
    extern __shared__ __half smem[];
    uint32_t acc[2][8][2];
    #pragma unroll
    for (int i = 0; i < 2; i++)
        #pragma unroll
        for (int j = 0; j < 8; j++) { acc[i][j][0] = 0u; acc[i][j][1] = 0u; }

    const int n0 = blockIdx.x * 128, m0 = blockIdx.y * 128, bb = blockIdx.z;
    const __half* A  = g_FG + ((size_t)bb * Np + m0) * 128;       // f
    const __half* Bp = g_FG + ((size_t)bb * Np + n0) * 128 + 64;  // g
    gemm_tile(A, 128, Bp, 128, 64, acc, smem);

    __half* Pb = g_P + (size_t)bb * Np * Np;
    const int lane = threadIdx.x & 31, warp = threadIdx.x >> 5;
    const int wm = warp & 3, wn = warp >> 2, g = lane >> 2, t4 = lane & 3;

    float rs[2][2] = {{0.f, 0.f}, {0.f, 0.f}};
    #pragma unroll
    for (int i = 0; i < 2; i++) {
        #pragma unroll
        for (int h = 0; h < 2; h++) {
            int r = m0 + wm * 32 + i * 16 + g + h * 8;
            #pragma unroll
            for (int j = 0; j < 8; j++) {
                int c = n0 + wn * 64 + j * 8 + 2 * t4;
                float2 s2 = __half22float2(*(__half2*)&acc[i][j][h]);
                __half2 ph = __floats2half2_rn(__expf(s2.x) * PSCALE,
                                               __expf(s2.y) * PSCALE);
                *(__half2*)&Pb[(size_t)r * Np + c] = ph;
                float2 pf = __half22float2(ph);   // round-tripped for exact l
                rs[i][h] += pf.x + pf.y;
            }
        }
    }
    #pragma unroll
    for (int i = 0; i < 2; i++) {
        #pragma unroll
        for (int h = 0; h < 2; h++) {
            float v = rs[i][h];
            v += __shfl_down_sync(0xffffffffu, v, 2, 4);
            v += __shfl_down_sync(0xffffffffu, v, 1, 4);
            if (t4 == 0) {
                int r = m0 + wm * 32 + i * 16 + g + h * 8;
                atomicAdd(&g_l[(size_t)bb * Np + r], v);
            }
        }
    }
}

// ---------------------------------------------------------------------------
// GEMM 3: out = gamma * (P @ Vt^T) / l + x   (per batch 4096x512, K=4096)
// ---------------------------------------------------------------------------
__global__ void __launch_bounds__(256, 2) gemm3_out(
    const float* __restrict__ x, const float* __restrict__ gamma,
    float* __restrict__ out)
{
    extern __shared__ __half smem[];
    uint32_t acc[2][8][2];
    #pragma unroll
    for (int i = 0; i < 2; i++)
        #pragma unroll
        for (int j = 0; j < 8; j++) { acc[i][j][0] = 0u; acc[i][j][1] = 0u; }

    const int n0 = blockIdx.x * 128, m0 = blockIdx.y * 128, bb = blockIdx.z;
    const __half* A  = g_P  + ((size_t)bb * Np + m0) * Np;
    const __half* Bp = g_Vt + ((size_t)bb * Cc + n0) * Np;
    gemm_tile(A, Np, Bp, Np, Np, acc, smem);

    const float gam = gamma[0];
    const int lane = threadIdx.x & 31, warp = threadIdx.x >> 5;
    const int wm = warp & 3, wn = warp >> 2, g = lane >> 2, t4 = lane & 3;

    #pragma unroll
    for (int i = 0; i < 2; i++) {
        #pragma unroll
        for (int h = 0; h < 2; h++) {
            int r = bb * Np + m0 + wm * 32 + i * 16 + g + h * 8;
            float inv = gam / g_l[r];
            #pragma unroll
            for (int j = 0; j < 8; j++) {
                int c = n0 + wn * 64 + j * 8 + 2 * t4;
                size_t o = (size_t)r * Cc + c;
                float2 a2 = __half22float2(*(__half2*)&acc[i][j][h]);
                float2 xv = *(const float2*)(x + o);
                float2 ov;
                ov.x = a2.x * inv + xv.x;
                ov.y = a2.y * inv + xv.y;
                *(float2*)(out + o) = ov;
            }
        }
    }
}

// ===========================================================================
extern "C" void kernel_launch(void* const* d_in, const int* in_sizes, int n_in,
                              void* d_out, int out_size) {
    const float* x     = (const float*)d_in[0];
    const float* kf    = (const float*)d_in[1];
    const float* kg    = (const float*)d_in[2];
    const float* kh    = (const float*)d_in[3];
    const float* gamma = (const float*)d_in[4];
    float* out = (float*)d_out;

    static bool attr_done = false;
    if (!attr_done) {
        cudaFuncSetAttribute(gemm1_qkv,   cudaFuncAttributeMaxDynamicSharedMemorySize, GEMM_SMEM);
        cudaFuncSetAttribute(gemm2_score, cudaFuncAttributeMaxDynamicSharedMemorySize, GEMM_SMEM);
        cudaFuncSetAttribute(gemm3_out,   cudaFuncAttributeMaxDynamicSharedMemorySize, GEMM_SMEM);
        attr_done = true;
    }

    convert_x<<<(NROWS * Cc / 4) / 256, 256>>>(x);
    pack_w<<<(NW * Cc) / 256, 256>>>(kf, kg, kh);
    zero_l<<<16, 1024>>>();
    gemm1_qkv<<<dim3(NW / 128, NROWS / 128), 256, GEMM_SMEM>>>();
    vtrans<<<dim3(64, 8, 4), 256>>>();
    gemm2_score<<<dim3(Np / 128, Np / 128, Bn), 256, GEMM_SMEM>>>();
    gemm3_out<<<dim3(Cc / 128, Np / 128, Bn), 256, GEMM_SMEM>>>(x, gamma, out);
}

// round 7
// speedup vs baseline: 1.0118x; 1.0118x over previous
#include <cuda_runtime.h>
#include <cuda_bf16.h>
#include <cuda_fp16.h>
#include <cstdint>

// Problem constants
#define Bn 4
#define Np 4096      // pixels per batch (64*64)
#define Cc 512
#define NW 640       // packed QKV output width: 64 f + 64 g + 512 v
#define NROWS (Bn*Np)
#define PSCALE 0.0625f   // P stored as exp(s)/16; cancels in P@V / rowsum(P)

// Scratch (static device allocations -- allowed)
__device__ __align__(1024) __half g_Xb[(size_t)NROWS * Cc];   // x in fp16
__device__ __align__(1024) __half g_Wt[(size_t)NW * Cc];      // packed weights [n][k]
__device__ __align__(1024) __half g_FG[(size_t)NROWS * 128];  // f (0-63), g (64-127)
__device__ __align__(1024) __half g_V [(size_t)Bn * Np * Cc]; // V natural [b][i][c]
__device__ __align__(1024) __half g_Vt[(size_t)Bn * Cc * Np]; // V transposed [b][c][i]
__device__ __align__(1024) __half g_P [(size_t)Bn * Np * Np]; // exp(S)/16, fp16
__device__ float g_l[NROWS];                                  // row sums of stored P

// ---------------------------------------------------------------------------
// mma.sync m16n8k16 fp16 -> fp16 accum
// ---------------------------------------------------------------------------
__device__ __forceinline__ void mma_f16(uint32_t c[2], const uint32_t a[4],
                                        uint32_t b0, uint32_t b1) {
    asm volatile(
        "mma.sync.aligned.m16n8k16.row.col.f16.f16.f16.f16 "
        "{%0,%1}, {%2,%3,%4,%5}, {%6,%7}, {%0,%1};\n"
        : "+r"(c[0]), "+r"(c[1])
        : "r"(a[0]), "r"(a[1]), "r"(a[2]), "r"(a[3]), "r"(b0), "r"(b1));
}
__device__ __forceinline__ void ldsm4(uint32_t& r0, uint32_t& r1, uint32_t& r2,
                                      uint32_t& r3, uint32_t addr) {
    asm volatile("ldmatrix.sync.aligned.m8n8.x4.shared.b16 {%0,%1,%2,%3}, [%4];"
                 : "=r"(r0), "=r"(r1), "=r"(r2), "=r"(r3) : "r"(addr));
}
__device__ __forceinline__ uint32_t smem_to_u32(const void* p) {
    uint32_t a;
    asm("{ .reg .u64 t; cvta.to.shared.u64 t, %1; cvt.u32.u64 %0, t; }" : "=r"(a) : "l"(p));
    return a;
}
__device__ __forceinline__ void cp16(uint32_t dst, const void* src) {
    asm volatile("cp.async.cg.shared.global [%0], [%1], 16;\n" :: "r"(dst), "l"(src));
}
#define CP_COMMIT() asm volatile("cp.async.commit_group;\n" ::: "memory")
#define CP_WAIT(n)  asm volatile("cp.async.wait_group %0;\n" :: "n"(n) : "memory")

#define TK  32
#define SA  40                        // smem row stride in fp16 (conflict-free)
#define STG (128 * SA)                // elements per staged tile (A or B)
#define NS  3                         // pipeline stages
#define GEMM_SMEM (NS * 2 * STG * 2)  // bytes = 61440 -> 3 CTAs/SM

// Block tile 128x128, K-tile 32, 256 threads (8 warps, 4x2 grid, 32x64 each).
// cp.async 3-stage pipeline, single barrier per K-iter; occupancy-based
// latency hiding (3 CTAs/SM), single-buffered fragments.
__device__ __forceinline__ void gemm_tile(
    const __half* __restrict__ Ag, int lda,
    const __half* __restrict__ Bg, int ldb,
    int K, uint32_t acc[2][8][2], __half* smem)
{
    const int tid = threadIdx.x, lane = tid & 31, warp = tid >> 5;
    const int wm = warp & 3, wn = warp >> 2;
    const uint32_t sbase = smem_to_u32(smem);
    const int r0 = tid >> 2;            // staging row 0..63 (+64 for 2nd chunk)
    const int c0 = (tid & 3) << 3;      // staging col {0,8,16,24}
    const int nk = K / TK;

    // Per-lane ldmatrix base byte-offsets within a stage buffer.
    const uint32_t offA0 = (uint32_t)((wm * 32 + ((lane >> 3) & 1) * 8 + (lane & 7)) * SA
                                      + (lane >> 4) * 8) * 2;
    const uint32_t offA1 = offA0 + 16 * SA * 2;
    const uint32_t offB0 = (uint32_t)(STG + (wn * 64 + (lane >> 4) * 8 + (lane & 7)) * SA
                                      + ((lane >> 3) & 1) * 8) * 2;

    auto issue = [&](int i) {
        const int s = i % NS;
        const uint32_t sa = sbase + (uint32_t)(s * 2 * STG) * 2;
        const uint32_t sb = sa + STG * 2;
        const int k0 = i * TK;
        cp16(sa + (r0 * SA + c0) * 2,        Ag + (size_t)r0 * lda + k0 + c0);
        cp16(sa + ((r0 + 64) * SA + c0) * 2, Ag + (size_t)(r0 + 64) * lda + k0 + c0);
        cp16(sb + (r0 * SA + c0) * 2,        Bg + (size_t)r0 * ldb + k0 + c0);
        cp16(sb + ((r0 + 64) * SA + c0) * 2, Bg + (size_t)(r0 + 64) * ldb + k0 + c0);
        CP_COMMIT();
    };

    // Prologue: fill up to NS-1 stages
    #pragma unroll
    for (int p = 0; p < NS - 1; p++)
        if (p < nk) issue(p);

    for (int i = 0; i < nk; i++) {
        if (i < nk - 1) CP_WAIT(1); else CP_WAIT(0);
        __syncthreads();                       // single barrier per iteration
        if (i + NS - 1 < nk) issue(i + NS - 1);

        const uint32_t bb = sbase + (uint32_t)((i % NS) * 2 * STG) * 2;
        #pragma unroll
        for (int ks = 0; ks < 2; ks++) {       // two k16 steps per K-tile
            const uint32_t kofs = (uint32_t)ks * 32;
            uint32_t a[2][4], b4[4][4];
            ldsm4(a[0][0], a[0][1], a[0][2], a[0][3], bb + offA0 + kofs);
            ldsm4(a[1][0], a[1][1], a[1][2], a[1][3], bb + offA1 + kofs);
            #pragma unroll
            for (int jp = 0; jp < 4; jp++)
                ldsm4(b4[jp][0], b4[jp][1], b4[jp][2], b4[jp][3],
                      bb + offB0 + (uint32_t)(jp * 16 * SA * 2) + kofs);
            #pragma unroll
            for (int ii = 0; ii < 2; ii++)
                #pragma unroll
                for (int jp = 0; jp < 4; jp++) {
                    mma_f16(acc[ii][2 * jp],     a[ii], b4[jp][0], b4[jp][1]);
                    mma_f16(acc[ii][2 * jp + 1], a[ii], b4[jp][2], b4[jp][3]);
                }
        }
    }
    __syncthreads();   // protect final buffers before caller reuses smem
}

// ---------------------------------------------------------------------------
// Prep kernels
// ---------------------------------------------------------------------------
__global__ void convert_x(const float* __restrict__ x) {
    size_t i = (size_t)blockIdx.x * 256 + threadIdx.x;
    float4 v = ((const float4*)x)[i];
    __half2 p0 = __floats2half2_rn(v.x, v.y);
    __half2 p1 = __floats2half2_rn(v.z, v.w);
    ((__half2*)g_Xb)[2 * i]     = p0;
    ((__half2*)g_Xb)[2 * i + 1] = p1;
}

__global__ void pack_w(const float* __restrict__ kf, const float* __restrict__ kg,
                       const float* __restrict__ kh) {
    int idx = blockIdx.x * 256 + threadIdx.x;
    int n = idx >> 9, k = idx & 511;
    float v;
    if (n < 64)       v = kf[k * 64 + n];
    else if (n < 128) v = kg[k * 64 + (n - 64)];
    else              v = kh[k * 512 + (n - 128)];
    g_Wt[idx] = __float2half(v);
}

__global__ void zero_l() {
    int i = blockIdx.x * 1024 + threadIdx.x;
    if (i < NROWS) g_l[i] = 0.f;
}

// ---------------------------------------------------------------------------
// GEMM 1: [f|g|v] = Xb @ W ; f/g -> g_FG, v -> g_V (natural, coalesced)
// ---------------------------------------------------------------------------
__global__ void __launch_bounds__(256, 3) gemm1_qkv() {
    extern __shared__ __half smem[];
    uint32_t acc[2][8][2];
    #pragma unroll
    for (int i = 0; i < 2; i++)
        #pragma unroll
        for (int j = 0; j < 8; j++) { acc[i][j][0] = 0u; acc[i][j][1] = 0u; }

    const int m0 = blockIdx.y * 128, n0 = blockIdx.x * 128;
    gemm_tile(g_Xb + (size_t)m0 * Cc, Cc, g_Wt + (size_t)n0 * Cc, Cc, Cc, acc, smem);

    const int lane = threadIdx.x & 31, warp = threadIdx.x >> 5;
    const int wm = warp & 3, wn = warp >> 2, g = lane >> 2, t4 = lane & 3;
    #pragma unroll
    for (int i = 0; i < 2; i++) {
        #pragma unroll
        for (int h = 0; h < 2; h++) {
            int r = m0 + wm * 32 + i * 16 + g + h * 8;
            #pragma unroll
            for (int j = 0; j < 8; j++) {
                int c = n0 + wn * 64 + j * 8 + 2 * t4;
                uint32_t p = acc[i][j][h];          // half2 at (r, c..c+1)
                if (n0 == 0) *(uint32_t*)&g_FG[(size_t)r * 128 + c] = p;
                else         *(uint32_t*)&g_V [(size_t)r * Cc + (c - 128)] = p;
            }
        }
    }
}

// ---------------------------------------------------------------------------
// Transpose V [b][i][c] -> Vt [b][c][i] (smem tiled, coalesced both sides)
// ---------------------------------------------------------------------------
__global__ void vtrans() {
    __shared__ __half t[64 * 72];
    const int bb = blockIdx.z, it = blockIdx.x, ct = blockIdx.y;
    const __half* src = g_V + ((size_t)bb * Np + it * 64) * Cc + ct * 64;
    #pragma unroll
    for (int k = 0; k < 2; k++) {
        int u = threadIdx.x + k * 256;
        int row = u >> 3, c8 = (u & 7) * 8;
        *(uint4*)(t + row * 72 + c8) = *(const uint4*)(src + (size_t)row * Cc + c8);
    }
    __syncthreads();
    __half* dst = g_Vt + ((size_t)bb * Cc + ct * 64) * Np + it * 64;
    #pragma unroll
    for (int k = 0; k < 2; k++) {
        int u = threadIdx.x + k * 256;
        int orow = u >> 3, i8 = (u & 7) * 8;
        __half tmp[8];
        #pragma unroll
        for (int q = 0; q < 8; q++) tmp[q] = t[(i8 + q) * 72 + orow];
        *(uint4*)(dst + (size_t)orow * Np + i8) = *(uint4*)tmp;
    }
}

// ---------------------------------------------------------------------------
// GEMM 2: P = exp(F @ G^T)/16 per batch, + fused row-sum atomics
// ---------------------------------------------------------------------------
__global__ void __launch_bounds__(256, 3) gemm2_score() {
    extern __shared__ __half smem[];
    uint32_t acc[2][8][2];
    #pragma unroll
    for (int i = 0; i < 2; i++)
        #pragma unroll
        for (int j = 0; j < 8; j++) { acc[i][j][0] = 0u; acc[i][j][1] = 0u; }

    const int n0 = blockIdx.x * 128, m0 = blockIdx.y * 128, bb = blockIdx.z;
    const __half* A  = g_FG + ((size_t)bb * Np + m0) * 128;       // f
    const __half* Bp = g_FG + ((size_t)bb * Np + n0) * 128 + 64;  // g
    gemm_tile(A, 128, Bp, 128, 64, acc, smem);

    __half* Pb = g_P + (size_t)bb * Np * Np;
    const int lane = threadIdx.x & 31, warp = threadIdx.x >> 5;
    const int wm = warp & 3, wn = warp >> 2, g = lane >> 2, t4 = lane & 3;

    float rs[2][2] = {{0.f, 0.f}, {0.f, 0.f}};
    #pragma unroll
    for (int i = 0; i < 2; i++) {
        #pragma unroll
        for (int h = 0; h < 2; h++) {
            int r = m0 + wm * 32 + i * 16 + g + h * 8;
            #pragma unroll
            for (int j = 0; j < 8; j++) {
                int c = n0 + wn * 64 + j * 8 + 2 * t4;
                float2 s2 = __half22float2(*(__half2*)&acc[i][j][h]);
                __half2 ph = __floats2half2_rn(__expf(s2.x) * PSCALE,
                                               __expf(s2.y) * PSCALE);
                *(__half2*)&Pb[(size_t)r * Np + c] = ph;
                float2 pf = __half22float2(ph);   // round-tripped for exact l
                rs[i][h] += pf.x + pf.y;
            }
        }
    }
    #pragma unroll
    for (int i = 0; i < 2; i++) {
        #pragma unroll
        for (int h = 0; h < 2; h++) {
            float v = rs[i][h];
            v += __shfl_down_sync(0xffffffffu, v, 2, 4);
            v += __shfl_down_sync(0xffffffffu, v, 1, 4);
            if (t4 == 0) {
                int r = m0 + wm * 32 + i * 16 + g + h * 8;
                atomicAdd(&g_l[(size_t)bb * Np + r], v);
            }
        }
    }
}

// ---------------------------------------------------------------------------
// GEMM 3: out = gamma * (P @ Vt^T) / l + x   (per batch 4096x512, K=4096)
// ---------------------------------------------------------------------------
__global__ void __launch_bounds__(256, 3) gemm3_out(
    const float* __restrict__ x, const float* __restrict__ gamma,
    float* __restrict__ out)
{
    extern __shared__ __half smem[];
    uint32_t acc[2][8][2];
    #pragma unroll
    for (int i = 0; i < 2; i++)
        #pragma unroll
        for (int j = 0; j < 8; j++) { acc[i][j][0] = 0u; acc[i][j][1] = 0u; }

    const int n0 = blockIdx.x * 128, m0 = blockIdx.y * 128, bb = blockIdx.z;
    const __half* A  = g_P  + ((size_t)bb * Np + m0) * Np;
    const __half* Bp = g_Vt + ((size_t)bb * Cc + n0) * Np;
    gemm_tile(A, Np, Bp, Np, Np, acc, smem);

    const float gam = gamma[0];
    const int lane = threadIdx.x & 31, warp = threadIdx.x >> 5;
    const int wm = warp & 3, wn = warp >> 2, g = lane >> 2, t4 = lane & 3;

    #pragma unroll
    for (int i = 0; i < 2; i++) {
        #pragma unroll
        for (int h = 0; h < 2; h++) {
            int r = bb * Np + m0 + wm * 32 + i * 16 + g + h * 8;
            float inv = gam / g_l[r];
            #pragma unroll
            for (int j = 0; j < 8; j++) {
                int c = n0 + wn * 64 + j * 8 + 2 * t4;
                size_t o = (size_t)r * Cc + c;
                float2 a2 = __half22float2(*(__half2*)&acc[i][j][h]);
                float2 xv = *(const float2*)(x + o);
                float2 ov;
                ov.x = a2.x * inv + xv.x;
                ov.y = a2.y * inv + xv.y;
                *(float2*)(out + o) = ov;
            }
        }
    }
}

// ===========================================================================
extern "C" void kernel_launch(void* const* d_in, const int* in_sizes, int n_in,
                              void* d_out, int out_size) {
    const float* x     = (const float*)d_in[0];
    const float* kf    = (const float*)d_in[1];
    const float* kg    = (const float*)d_in[2];
    const float* kh    = (const float*)d_in[3];
    const float* gamma = (const float*)d_in[4];
    float* out = (float*)d_out;

    static bool attr_done = false;
    if (!attr_done) {
        cudaFuncSetAttribute(gemm1_qkv,   cudaFuncAttributeMaxDynamicSharedMemorySize, GEMM_SMEM);
        cudaFuncSetAttribute(gemm2_score, cudaFuncAttributeMaxDynamicSharedMemorySize, GEMM_SMEM);
        cudaFuncSetAttribute(gemm3_out,   cudaFuncAttributeMaxDynamicSharedMemorySize, GEMM_SMEM);
        attr_done = true;
    }

    convert_x<<<(NROWS * Cc / 4) / 256, 256>>>(x);
    pack_w<<<(NW * Cc) / 256, 256>>>(kf, kg, kh);
    zero_l<<<16, 1024>>>();
    gemm1_qkv<<<dim3(NW / 128, NROWS / 128), 256, GEMM_SMEM>>>();
    vtrans<<<dim3(64, 8, 4), 256>>>();
    gemm2_score<<<dim3(Np / 128, Np / 128, Bn), 256, GEMM_SMEM>>>();
    gemm3_out<<<dim3(Cc / 128, Np / 128, Bn), 256, GEMM_SMEM>>>(x, gamma, out);
}

// round 8
// speedup vs baseline: 1.2419x; 1.2275x over previous
#include <cuda_runtime.h>
#include <cuda_bf16.h>
#include <cuda_fp16.h>
#include <cstdint>

// Problem constants
#define Bn 4
#define Np 4096      // pixels per batch (64*64)
#define Cc 512
#define NW 640       // packed QKV output width: 64 f + 64 g + 512 v
#define NROWS (Bn*Np)
#define PSCALE 0.0625f   // P stored as exp(s)/16; cancels in P@V / rowsum(P)

// Scratch (static device allocations -- allowed)
__device__ __align__(1024) __half g_Xb[(size_t)NROWS * Cc];   // x in fp16
__device__ __align__(1024) __half g_Wt[(size_t)NW * Cc];      // packed weights [n][k]
__device__ __align__(1024) __half g_FG[(size_t)NROWS * 128];  // f (0-63), g (64-127)
__device__ __align__(1024) __half g_V [(size_t)Bn * Np * Cc]; // V natural [b][i][c]
__device__ __align__(1024) __half g_Vt[(size_t)Bn * Cc * Np]; // V transposed [b][c][i]
__device__ __align__(1024) __half g_P [(size_t)Bn * Np * Np]; // exp(S)/16, fp16
__device__ float g_l[NROWS];                                  // row sums of stored P

// ---------------------------------------------------------------------------
// mma.sync m16n8k16 fp16 -> fp16 accum
// ---------------------------------------------------------------------------
__device__ __forceinline__ void mma_f16(uint32_t c[2], const uint32_t a[4],
                                        uint32_t b0, uint32_t b1) {
    asm volatile(
        "mma.sync.aligned.m16n8k16.row.col.f16.f16.f16.f16 "
        "{%0,%1}, {%2,%3,%4,%5}, {%6,%7}, {%0,%1};\n"
        : "+r"(c[0]), "+r"(c[1])
        : "r"(a[0]), "r"(a[1]), "r"(a[2]), "r"(a[3]), "r"(b0), "r"(b1));
}
__device__ __forceinline__ void ldsm4(uint32_t* r, uint32_t addr) {
    asm volatile("ldmatrix.sync.aligned.m8n8.x4.shared.b16 {%0,%1,%2,%3}, [%4];"
                 : "=r"(r[0]), "=r"(r[1]), "=r"(r[2]), "=r"(r[3]) : "r"(addr));
}
__device__ __forceinline__ uint32_t smem_to_u32(const void* p) {
    uint32_t a;
    asm("{ .reg .u64 t; cvta.to.shared.u64 t, %1; cvt.u32.u64 %0, t; }" : "=r"(a) : "l"(p));
    return a;
}
__device__ __forceinline__ void cp16(uint32_t dst, const void* src) {
    asm volatile("cp.async.cg.shared.global [%0], [%1], 16;\n" :: "r"(dst), "l"(src));
}
#define CP_COMMIT() asm volatile("cp.async.commit_group;\n" ::: "memory")
#define CP_WAIT0()  asm volatile("cp.async.wait_group 0;\n" ::: "memory")

#define TKE   64                 // K-tile in fp16 elements (128 bytes per row)
#define TILEB (128 * 128)        // bytes per staged tile (128 rows x 128B, SW128)
#define NS    2                  // double buffer
#define GEMM_SMEM (NS * 2 * TILEB)   // 65536 bytes -> 3 CTAs/SM

// Block tile 128x128, K-tile 64, 256 threads (8 warps, 4x2 grid, 32x64 each).
// SW128 XOR-swizzled stages (no padding), cp.async double buffer, ONE barrier
// per 64-wide K-tile, 3 CTAs/SM for cross-warp latency hiding.
__device__ __forceinline__ void gemm_tile(
    const __half* __restrict__ Ag, int lda,
    const __half* __restrict__ Bg, int ldb,
    int K, uint32_t acc[2][8][2], __half* smem)
{
    const int tid = threadIdx.x, lane = tid & 31, warp = tid >> 5;
    const int wm = warp & 3, wn = warp >> 2;
    const uint32_t sbase = smem_to_u32(smem);
    const int srow = tid >> 3;          // staging row 0..31 (+32*q)
    const int schunk = tid & 7;         // 16B chunk within 128B row
    const int nk = K / TKE;

    const uint32_t l7  = lane & 7;
    const uint32_t hiA = lane >> 4;            // A: k-half from lane
    const uint32_t hiB = (lane >> 3) & 1;      // B: k-half from lane
    const uint32_t rowA = (uint32_t)(wm * 32 + ((lane >> 3) & 1) * 8) + l7;
    const uint32_t rowB = (uint32_t)(wn * 64 + (lane >> 4) * 8) + l7;

    auto issue = [&](int i) {
        const uint32_t sa = sbase + (uint32_t)((i & 1) * 2 * TILEB);
        const uint32_t sb = sa + TILEB;
        const int k0 = i * TKE;
        const uint32_t pch = (uint32_t)(schunk ^ (srow & 7)) * 16;
        #pragma unroll
        for (int q = 0; q < 4; q++) {
            const int row = srow + q * 32;
            const uint32_t soff = (uint32_t)row * 128 + pch;
            cp16(sa + soff, (const char*)(Ag + (size_t)row * lda + k0) + schunk * 16);
            cp16(sb + soff, (const char*)(Bg + (size_t)row * ldb + k0) + schunk * 16);
        }
        CP_COMMIT();
    };

    issue(0);   // prologue

    for (int i = 0; i < nk; i++) {
        CP_WAIT0();
        __syncthreads();                 // single barrier per K-tile
        if (i + 1 < nk) issue(i + 1);

        const uint32_t bb = sbase + (uint32_t)((i & 1) * 2 * TILEB);
        #pragma unroll
        for (int ks = 0; ks < 4; ks++) {             // four k16 steps
            const uint32_t pa = (((uint32_t)(2 * ks) + hiA) ^ l7) << 4;
            const uint32_t pb = (((uint32_t)(2 * ks) + hiB) ^ l7) << 4;
            uint32_t a[2][4], b4[4][4];
            ldsm4(a[0], bb + rowA * 128 + pa);
            ldsm4(a[1], bb + (rowA + 16) * 128 + pa);
            #pragma unroll
            for (int jp = 0; jp < 4; jp++)
                ldsm4(b4[jp], bb + TILEB + (rowB + (uint32_t)(jp * 16)) * 128 + pb);
            #pragma unroll
            for (int ii = 0; ii < 2; ii++)
                #pragma unroll
                for (int jp = 0; jp < 4; jp++) {
                    mma_f16(acc[ii][2 * jp],     a[ii], b4[jp][0], b4[jp][1]);
                    mma_f16(acc[ii][2 * jp + 1], a[ii], b4[jp][2], b4[jp][3]);
                }
        }
    }
    __syncthreads();
}

// ---------------------------------------------------------------------------
// Prep kernels
// ---------------------------------------------------------------------------
__global__ void convert_x(const float* __restrict__ x) {
    size_t i = (size_t)blockIdx.x * 256 + threadIdx.x;
    float4 v = ((const float4*)x)[i];
    __half2 p0 = __floats2half2_rn(v.x, v.y);
    __half2 p1 = __floats2half2_rn(v.z, v.w);
    ((__half2*)g_Xb)[2 * i]     = p0;
    ((__half2*)g_Xb)[2 * i + 1] = p1;
}

__global__ void pack_w(const float* __restrict__ kf, const float* __restrict__ kg,
                       const float* __restrict__ kh) {
    int idx = blockIdx.x * 256 + threadIdx.x;
    int n = idx >> 9, k = idx & 511;
    float v;
    if (n < 64)       v = kf[k * 64 + n];
    else if (n < 128) v = kg[k * 64 + (n - 64)];
    else              v = kh[k * 512 + (n - 128)];
    g_Wt[idx] = __float2half(v);
}

__global__ void zero_l() {
    int i = blockIdx.x * 1024 + threadIdx.x;
    if (i < NROWS) g_l[i] = 0.f;
}

// ---------------------------------------------------------------------------
// GEMM 1: [f|g|v] = Xb @ W ; f/g -> g_FG, v -> g_V (natural, coalesced)
// ---------------------------------------------------------------------------
__global__ void __launch_bounds__(256, 3) gemm1_qkv() {
    extern __shared__ __half smem[];
    uint32_t acc[2][8][2];
    #pragma unroll
    for (int i = 0; i < 2; i++)
        #pragma unroll
        for (int j = 0; j < 8; j++) { acc[i][j][0] = 0u; acc[i][j][1] = 0u; }

    const int m0 = blockIdx.y * 128, n0 = blockIdx.x * 128;
    gemm_tile(g_Xb + (size_t)m0 * Cc, Cc, g_Wt + (size_t)n0 * Cc, Cc, Cc, acc, smem);

    const int lane = threadIdx.x & 31, warp = threadIdx.x >> 5;
    const int wm = warp & 3, wn = warp >> 2, g = lane >> 2, t4 = lane & 3;
    #pragma unroll
    for (int i = 0; i < 2; i++) {
        #pragma unroll
        for (int h = 0; h < 2; h++) {
            int r = m0 + wm * 32 + i * 16 + g + h * 8;
            #pragma unroll
            for (int j = 0; j < 8; j++) {
                int c = n0 + wn * 64 + j * 8 + 2 * t4;
                uint32_t p = acc[i][j][h];          // half2 at (r, c..c+1)
                if (n0 == 0) *(uint32_t*)&g_FG[(size_t)r * 128 + c] = p;
                else         *(uint32_t*)&g_V [(size_t)r * Cc + (c - 128)] = p;
            }
        }
    }
}

// ---------------------------------------------------------------------------
// Transpose V [b][i][c] -> Vt [b][c][i] (smem tiled, coalesced both sides)
// ---------------------------------------------------------------------------
__global__ void vtrans() {
    __shared__ __half t[64 * 72];
    const int bb = blockIdx.z, it = blockIdx.x, ct = blockIdx.y;
    const __half* src = g_V + ((size_t)bb * Np + it * 64) * Cc + ct * 64;
    #pragma unroll
    for (int k = 0; k < 2; k++) {
        int u = threadIdx.x + k * 256;
        int row = u >> 3, c8 = (u & 7) * 8;
        *(uint4*)(t + row * 72 + c8) = *(const uint4*)(src + (size_t)row * Cc + c8);
    }
    __syncthreads();
    __half* dst = g_Vt + ((size_t)bb * Cc + ct * 64) * Np + it * 64;
    #pragma unroll
    for (int k = 0; k < 2; k++) {
        int u = threadIdx.x + k * 256;
        int orow = u >> 3, i8 = (u & 7) * 8;
        __half tmp[8];
        #pragma unroll
        for (int q = 0; q < 8; q++) tmp[q] = t[(i8 + q) * 72 + orow];
        *(uint4*)(dst + (size_t)orow * Np + i8) = *(uint4*)tmp;
    }
}

// ---------------------------------------------------------------------------
// GEMM 2: P = exp(F @ G^T)/16 per batch, + fused row-sum atomics
// ---------------------------------------------------------------------------
__global__ void __launch_bounds__(256, 3) gemm2_score() {
    extern __shared__ __half smem[];
    uint32_t acc[2][8][2];
    #pragma unroll
    for (int i = 0; i < 2; i++)
        #pragma unroll
        for (int j = 0; j < 8; j++) { acc[i][j][0] = 0u; acc[i][j][1] = 0u; }

    const int n0 = blockIdx.x * 128, m0 = blockIdx.y * 128, bb = blockIdx.z;
    const __half* A  = g_FG + ((size_t)bb * Np + m0) * 128;       // f
    const __half* Bp = g_FG + ((size_t)bb * Np + n0) * 128 + 64;  // g
    gemm_tile(A, 128, Bp, 128, 64, acc, smem);

    __half* Pb = g_P + (size_t)bb * Np * Np;
    const int lane = threadIdx.x & 31, warp = threadIdx.x >> 5;
    const int wm = warp & 3, wn = warp >> 2, g = lane >> 2, t4 = lane & 3;

    float rs[2][2] = {{0.f, 0.f}, {0.f, 0.f}};
    #pragma unroll
    for (int i = 0; i < 2; i++) {
        #pragma unroll
        for (int h = 0; h < 2; h++) {
            int r = m0 + wm * 32 + i * 16 + g + h * 8;
            #pragma unroll
            for (int j = 0; j < 8; j++) {
                int c = n0 + wn * 64 + j * 8 + 2 * t4;
                float2 s2 = __half22float2(*(__half2*)&acc[i][j][h]);
                __half2 ph = __floats2half2_rn(__expf(s2.x) * PSCALE,
                                               __expf(s2.y) * PSCALE);
                *(__half2*)&Pb[(size_t)r * Np + c] = ph;
                float2 pf = __half22float2(ph);   // round-tripped for exact l
                rs[i][h] += pf.x + pf.y;
            }
        }
    }
    #pragma unroll
    for (int i = 0; i < 2; i++) {
        #pragma unroll
        for (int h = 0; h < 2; h++) {
            float v = rs[i][h];
            v += __shfl_down_sync(0xffffffffu, v, 2, 4);
            v += __shfl_down_sync(0xffffffffu, v, 1, 4);
            if (t4 == 0) {
                int r = m0 + wm * 32 + i * 16 + g + h * 8;
                atomicAdd(&g_l[(size_t)bb * Np + r], v);
            }
        }
    }
}

// ---------------------------------------------------------------------------
// GEMM 3: out = gamma * (P @ Vt^T) / l + x   (per batch 4096x512, K=4096)
// ---------------------------------------------------------------------------
__global__ void __launch_bounds__(256, 3) gemm3_out(
    const float* __restrict__ x, const float* __restrict__ gamma,
    float* __restrict__ out)
{
    extern __shared__ __half smem[];
    uint32_t acc[2][8][2];
    #pragma unroll
    for (int i = 0; i < 2; i++)
        #pragma unroll
        for (int j = 0; j < 8; j++) { acc[i][j][0] = 0u; acc[i][j][1] = 0u; }

    const int n0 = blockIdx.x * 128, m0 = blockIdx.y * 128, bb = blockIdx.z;
    const __half* A  = g_P  + ((size_t)bb * Np + m0) * Np;
    const __half* Bp = g_Vt + ((size_t)bb * Cc + n0) * Np;
    gemm_tile(A, Np, Bp, Np, Np, acc, smem);

    const float gam = gamma[0];
    const int lane = threadIdx.x & 31, warp = threadIdx.x >> 5;
    const int wm = warp & 3, wn = warp >> 2, g = lane >> 2, t4 = lane & 3;

    #pragma unroll
    for (int i = 0; i < 2; i++) {
        #pragma unroll
        for (int h = 0; h < 2; h++) {
            int r = bb * Np + m0 + wm * 32 + i * 16 + g + h * 8;
            float inv = gam / g_l[r];
            #pragma unroll
            for (int j = 0; j < 8; j++) {
                int c = n0 + wn * 64 + j * 8 + 2 * t4;
                size_t o = (size_t)r * Cc + c;
                float2 a2 = __half22float2(*(__half2*)&acc[i][j][h]);
                float2 xv = *(const float2*)(x + o);
                float2 ov;
                ov.x = a2.x * inv + xv.x;
                ov.y = a2.y * inv + xv.y;
                *(float2*)(out + o) = ov;
            }
        }
    }
}

// ===========================================================================
extern "C" void kernel_launch(void* const* d_in, const int* in_sizes, int n_in,
                              void* d_out, int out_size) {
    const float* x     = (const float*)d_in[0];
    const float* kf    = (const float*)d_in[1];
    const float* kg    = (const float*)d_in[2];
    const float* kh    = (const float*)d_in[3];
    const float* gamma = (const float*)d_in[4];
    float* out = (float*)d_out;

    static bool attr_done = false;
    if (!attr_done) {
        cudaFuncSetAttribute(gemm1_qkv,   cudaFuncAttributeMaxDynamicSharedMemorySize, GEMM_SMEM);
        cudaFuncSetAttribute(gemm2_score, cudaFuncAttributeMaxDynamicSharedMemorySize, GEMM_SMEM);
        cudaFuncSetAttribute(gemm3_out,   cudaFuncAttributeMaxDynamicSharedMemorySize, GEMM_SMEM);
        attr_done = true;
    }

    convert_x<<<(NROWS * Cc / 4) / 256, 256>>>(x);
    pack_w<<<(NW * Cc) / 256, 256>>>(kf, kg, kh);
    zero_l<<<16, 1024>>>();
    gemm1_qkv<<<dim3(NW / 128, NROWS / 128), 256, GEMM_SMEM>>>();
    vtrans<<<dim3(64, 8, 4), 256>>>();
    gemm2_score<<<dim3(Np / 128, Np / 128, Bn), 256, GEMM_SMEM>>>();
    gemm3_out<<<dim3(Cc / 128, Np / 128, Bn), 256, GEMM_SMEM>>>(x, gamma, out);
}